// round 1
// baseline (speedup 1.0000x reference)
#include <cuda_runtime.h>

// Problem constants (from reference)
#define B_  8
#define C_  32
#define H_  256
#define W_  512
#define D_  48

// Tiling
#define WT      4            // w per thread (float4)
#define DT      8            // d per thread
#define NWBLK   (W_ / WT)    // 128
#define NDBLK   (D_ / DT)    // 6
#define NTHREADS (NWBLK * NDBLK)   // 768

#define PAD     64           // zero pad in front of y row (>= D_)
#define YSTRIDE (PAD + W_)   // 576 floats per c row of y

// dynamic smem: x[C][W] + y[C][YSTRIDE]
#define SMEM_X_FLOATS (C_ * W_)
#define SMEM_Y_FLOATS (C_ * YSTRIDE)
#define SMEM_BYTES ((SMEM_X_FLOATS + SMEM_Y_FLOATS) * 4)

__global__ __launch_bounds__(NTHREADS, 1)
void corr_kernel(const float* __restrict__ x,
                 const float* __restrict__ y,
                 float* __restrict__ out)
{
    extern __shared__ float smem[];
    float* x_s = smem;                   // [C][W]
    float* y_s = smem + SMEM_X_FLOATS;   // [C][YSTRIDE], first PAD floats per row = 0

    const int bh = blockIdx.x;           // 0 .. B*H-1
    const int b  = bh / H_;
    const int h  = bh % H_;
    const int tid = threadIdx.x;

    // ---- load x row [C][W] as float4 (each element read once, coalesced) ----
    {
        const float4* xg = reinterpret_cast<const float4*>(
            x + ((size_t)(b * C_) * H_ + h) * W_);
        // global rows for consecutive c are H_*W_ floats apart => H_*W_/4 float4
        const int rowstride4 = (H_ * W_) / 4;
        float4* xs4 = reinterpret_cast<float4*>(x_s);
        #pragma unroll 1
        for (int i = tid; i < C_ * (W_ / 4); i += NTHREADS) {
            int c = i >> 7;              // / (W_/4) = /128
            int j = i & 127;
            xs4[c * (W_ / 4) + j] = xg[c * rowstride4 + j];
        }
    }
    // ---- zero pad region of y rows ----
    {
        float4* ys4 = reinterpret_cast<float4*>(y_s);
        for (int i = tid; i < C_ * (PAD / 4); i += NTHREADS) {
            int c = i >> 4;              // / (PAD/4) = /16
            int j = i & 15;
            ys4[c * (YSTRIDE / 4) + j] = make_float4(0.f, 0.f, 0.f, 0.f);
        }
    }
    // ---- load y row [C][W] into padded smem ----
    {
        const float4* yg = reinterpret_cast<const float4*>(
            y + ((size_t)(b * C_) * H_ + h) * W_);
        const int rowstride4 = (H_ * W_) / 4;
        float4* ys4 = reinterpret_cast<float4*>(y_s);
        #pragma unroll 1
        for (int i = tid; i < C_ * (W_ / 4); i += NTHREADS) {
            int c = i >> 7;
            int j = i & 127;
            ys4[c * (YSTRIDE / 4) + (PAD / 4) + j] = yg[c * rowstride4 + j];
        }
    }
    __syncthreads();

    // ---- compute: thread owns w tile [w0, w0+4) x d tile [d0, d0+8) ----
    const int wblk = tid & (NWBLK - 1);      // tid % 128
    const int dblk = tid >> 7;               // tid / 128 (0..5)
    const int w0 = wblk * WT;
    const int d0 = dblk * DT;

    // y window (aligned float4): start index s = PAD + w0 - d0 - 8
    const int s = PAD + w0 - d0 - 8;         // >= 16, multiple of 4

    float acc[DT][WT];
    #pragma unroll
    for (int dd = 0; dd < DT; dd++)
        #pragma unroll
        for (int i = 0; i < WT; i++) acc[dd][i] = 0.f;

    #pragma unroll 4
    for (int c = 0; c < C_; c++) {
        const float* xr = x_s + c * W_;
        const float* yr = y_s + c * YSTRIDE;
        float4 xv  = *reinterpret_cast<const float4*>(xr + w0);
        float4 y0v = *reinterpret_cast<const float4*>(yr + s);
        float4 y1v = *reinterpret_cast<const float4*>(yr + s + 4);
        float4 y2v = *reinterpret_cast<const float4*>(yr + s + 8);
        float yb[12] = { y0v.x, y0v.y, y0v.z, y0v.w,
                         y1v.x, y1v.y, y1v.z, y1v.w,
                         y2v.x, y2v.y, y2v.z, y2v.w };
        float xb[4] = { xv.x, xv.y, xv.z, xv.w };
        #pragma unroll
        for (int dd = 0; dd < DT; dd++) {
            #pragma unroll
            for (int i = 0; i < WT; i++) {
                // y index: s + 8 - dd + i  (relative to window start)
                acc[dd][i] = fmaf(xb[i], yb[8 - dd + i], acc[dd][i]);
            }
        }
    }

    // ---- store (mean over C): all outputs written; pad-zeros give exact 0 for w<d ----
    const float inv = 1.0f / (float)C_;
    #pragma unroll
    for (int dd = 0; dd < DT; dd++) {
        int d = d0 + dd;
        float4 v = make_float4(acc[dd][0] * inv, acc[dd][1] * inv,
                               acc[dd][2] * inv, acc[dd][3] * inv);
        float* op = out + (((size_t)(b * D_ + d)) * H_ + h) * W_ + w0;
        *reinterpret_cast<float4*>(op) = v;
    }
}

extern "C" void kernel_launch(void* const* d_in, const int* in_sizes, int n_in,
                              void* d_out, int out_size)
{
    const float* x = (const float*)d_in[0];
    const float* y = (const float*)d_in[1];
    float* out = (float*)d_out;

    static bool attr_set = false;
    if (!attr_set) {
        cudaFuncSetAttribute(corr_kernel,
                             cudaFuncAttributeMaxDynamicSharedMemorySize,
                             SMEM_BYTES);
        attr_set = true;
    }

    corr_kernel<<<B_ * H_, NTHREADS, SMEM_BYTES>>>(x, y, out);
}

// round 2
// speedup vs baseline: 1.5007x; 1.5007x over previous
#include <cuda_runtime.h>

// Problem constants
#define B_  8
#define C_  32
#define H_  256
#define W_  512
#define D_  48

// Tiling
#define WTILE   256              // w per CTA
#define NWT     (W_ / WTILE)     // 2 tiles
#define WT      4                // w per thread (float4)
#define DT      8                // d per thread
#define NWBLK   (WTILE / WT)     // 64
#define NDBLK   (D_ / DT)        // 6
#define NTHREADS (NWBLK * NDBLK) // 384

#define PAD     64               // zero/halo pad in front of y tile (>= D_)
#define YROW    (PAD + WTILE)    // 320 floats per c row of y

#define SMEM_X_FLOATS (C_ * WTILE)   // 8192
#define SMEM_Y_FLOATS (C_ * YROW)    // 10240
#define SMEM_BYTES ((SMEM_X_FLOATS + SMEM_Y_FLOATS) * 4)  // 73728

__device__ __forceinline__ unsigned long long pack2(float lo, float hi) {
    unsigned long long r;
    asm("mov.b64 %0, {%1, %2};" : "=l"(r) : "f"(lo), "f"(hi));
    return r;
}
__device__ __forceinline__ void unpack2(unsigned long long v, float& lo, float& hi) {
    asm("mov.b64 {%0, %1}, %2;" : "=f"(lo), "=f"(hi) : "l"(v));
}
// packed dual fp32 fma: acc.{x,y} += a.{x,y} * b.{x,y}
__device__ __forceinline__ void ffma2(unsigned long long& acc,
                                      unsigned long long a, unsigned long long b) {
    asm("fma.rn.f32x2 %0, %1, %2, %0;" : "+l"(acc) : "l"(a), "l"(b));
}

__global__ __launch_bounds__(NTHREADS, 2)
void corr_kernel(const float* __restrict__ x,
                 const float* __restrict__ y,
                 float* __restrict__ out)
{
    extern __shared__ float smem[];
    float* x_s = smem;                   // [C][WTILE]
    float* y_s = smem + SMEM_X_FLOATS;   // [C][YROW]

    const int blk = blockIdx.x;
    const int wtile = blk & (NWT - 1);   // 0..1
    const int bh = blk >> 1;             // 0..B*H-1
    const int b  = bh / H_;
    const int h  = bh % H_;
    const int w0t = wtile * WTILE;
    const int tid = threadIdx.x;

    const int rowstride4 = (H_ * W_) / 4;

    // ---- load x tile [C][WTILE] ----
    {
        const float4* xg = reinterpret_cast<const float4*>(
            x + ((size_t)(b * C_) * H_ + h) * W_ + w0t);
        float4* xs4 = reinterpret_cast<float4*>(x_s);
        #pragma unroll 1
        for (int i = tid; i < C_ * (WTILE / 4); i += NTHREADS) {
            int c = i >> 6;              // / 64
            int j = i & 63;
            xs4[c * (WTILE / 4) + j] = xg[c * rowstride4 + j];
        }
    }
    // ---- pad region of y rows: zero (tile 0) or halo from global (tile 1) ----
    {
        float4* ys4 = reinterpret_cast<float4*>(y_s);
        if (w0t == 0) {
            for (int i = tid; i < C_ * (PAD / 4); i += NTHREADS) {
                int c = i >> 4;          // / 16
                int j = i & 15;
                ys4[c * (YROW / 4) + j] = make_float4(0.f, 0.f, 0.f, 0.f);
            }
        } else {
            const float4* yg = reinterpret_cast<const float4*>(
                y + ((size_t)(b * C_) * H_ + h) * W_ + w0t - PAD);
            for (int i = tid; i < C_ * (PAD / 4); i += NTHREADS) {
                int c = i >> 4;
                int j = i & 15;
                ys4[c * (YROW / 4) + j] = yg[c * rowstride4 + j];
            }
        }
    }
    // ---- load y main tile [C][WTILE] into padded smem ----
    {
        const float4* yg = reinterpret_cast<const float4*>(
            y + ((size_t)(b * C_) * H_ + h) * W_ + w0t);
        float4* ys4 = reinterpret_cast<float4*>(y_s);
        #pragma unroll 1
        for (int i = tid; i < C_ * (WTILE / 4); i += NTHREADS) {
            int c = i >> 6;
            int j = i & 63;
            ys4[c * (YROW / 4) + (PAD / 4) + j] = yg[c * rowstride4 + j];
        }
    }
    __syncthreads();

    // ---- compute: thread owns local w tile [w0, w0+4) x d tile [d0, d0+8) ----
    const int wblk = tid & (NWBLK - 1);      // tid % 64
    const int dblk = tid >> 6;               // 0..5
    const int w0 = wblk * WT;                // local
    const int d0 = dblk * DT;

    // y window start: covers yb[0..11] = y_s[c][s .. s+11]
    // acc[dd][i] needs y at (PAD + w0 - d0 - 8) + (8 - dd + i)
    const int s = PAD + w0 - d0 - 8;         // >= 16, multiple of 4

    unsigned long long acc2[DT][2];
    #pragma unroll
    for (int dd = 0; dd < DT; dd++) { acc2[dd][0] = 0ull; acc2[dd][1] = 0ull; }

    #pragma unroll 2
    for (int c = 0; c < C_; c++) {
        const float* xr = x_s + c * WTILE;
        const float* yr = y_s + c * YROW;
        float4 xv  = *reinterpret_cast<const float4*>(xr + w0);
        float4 y0v = *reinterpret_cast<const float4*>(yr + s);
        float4 y1v = *reinterpret_cast<const float4*>(yr + s + 4);
        float4 y2v = *reinterpret_cast<const float4*>(yr + s + 8);
        float yb[12] = { y0v.x, y0v.y, y0v.z, y0v.w,
                         y1v.x, y1v.y, y1v.z, y1v.w,
                         y2v.x, y2v.y, y2v.z, y2v.w };
        unsigned long long x01 = pack2(xv.x, xv.y);
        unsigned long long x23 = pack2(xv.z, xv.w);
        // overlapping y pairs p[k] = (yb[k], yb[k+1]), k = 1..10
        unsigned long long p[11];
        #pragma unroll
        for (int k = 1; k <= 10; k++) p[k] = pack2(yb[k], yb[k + 1]);
        #pragma unroll
        for (int dd = 0; dd < DT; dd++) {
            ffma2(acc2[dd][0], x01, p[8 - dd]);    // w0,w1
            ffma2(acc2[dd][1], x23, p[10 - dd]);   // w2,w3
        }
    }

    // ---- store (mean over C) ----
    const float inv = 1.0f / (float)C_;
    #pragma unroll
    for (int dd = 0; dd < DT; dd++) {
        int d = d0 + dd;
        float a0, a1, a2, a3;
        unpack2(acc2[dd][0], a0, a1);
        unpack2(acc2[dd][1], a2, a3);
        float4 v = make_float4(a0 * inv, a1 * inv, a2 * inv, a3 * inv);
        float* op = out + (((size_t)(b * D_ + d)) * H_ + h) * W_ + w0t + w0;
        *reinterpret_cast<float4*>(op) = v;
    }
}

extern "C" void kernel_launch(void* const* d_in, const int* in_sizes, int n_in,
                              void* d_out, int out_size)
{
    const float* x = (const float*)d_in[0];
    const float* y = (const float*)d_in[1];
    float* out = (float*)d_out;

    static bool attr_set = false;
    if (!attr_set) {
        cudaFuncSetAttribute(corr_kernel,
                             cudaFuncAttributeMaxDynamicSharedMemorySize,
                             SMEM_BYTES);
        attr_set = true;
    }

    corr_kernel<<<B_ * H_ * NWT, NTHREADS, SMEM_BYTES>>>(x, y, out);
}

// round 3
// speedup vs baseline: 2.2855x; 1.5229x over previous
#include <cuda_runtime.h>
#include <cstdint>

// Problem constants
#define B_  8
#define C_  32
#define H_  256
#define W_  512
#define D_  48

// Tiling
#define WTILE   256
#define NWT     (W_ / WTILE)       // 2
#define WT      4                  // w per thread
#define DT      8                  // d per thread
#define NWBLK   (WTILE / WT)       // 64
#define NDBLK   (D_ / DT)          // 6
#define NTHREADS (NWBLK * NDBLK)   // 384

#define PAD     64
#define YROW    (PAD + WTILE)      // 320

// c-chunk pipeline
#define CH      8
#define NCH     (C_ / CH)          // 4

#define XCH_FLOATS (CH * WTILE)    // 2048
#define YCH_FLOATS (CH * YROW)     // 2560
#define SMEM_BYTES ((2 * (XCH_FLOATS + YCH_FLOATS)) * 4)   // 36864

__device__ __forceinline__ unsigned long long pack2(float lo, float hi) {
    unsigned long long r;
    asm("mov.b64 %0, {%1, %2};" : "=l"(r) : "f"(lo), "f"(hi));
    return r;
}
__device__ __forceinline__ void unpack2(unsigned long long v, float& lo, float& hi) {
    asm("mov.b64 {%0, %1}, %2;" : "=f"(lo), "=f"(hi) : "l"(v));
}
__device__ __forceinline__ void ffma2(unsigned long long& acc,
                                      unsigned long long a, unsigned long long b) {
    asm("fma.rn.f32x2 %0, %1, %2, %0;" : "+l"(acc) : "l"(a), "l"(b));
}
__device__ __forceinline__ void cp_async16(uint32_t saddr, const void* gptr) {
    asm volatile("cp.async.cg.shared.global [%0], [%1], 16;"
                 :: "r"(saddr), "l"(gptr));
}
__device__ __forceinline__ void cp_commit() {
    asm volatile("cp.async.commit_group;");
}
__device__ __forceinline__ void cp_wait1() {
    asm volatile("cp.async.wait_group 1;");
}
__device__ __forceinline__ void cp_wait0() {
    asm volatile("cp.async.wait_group 0;");
}

__global__ __launch_bounds__(NTHREADS, 2)
void corr_kernel(const float* __restrict__ x,
                 const float* __restrict__ y,
                 float* __restrict__ out)
{
    extern __shared__ float smem[];
    float* x_s = smem;                       // [2][CH][WTILE]
    float* y_s = smem + 2 * XCH_FLOATS;      // [2][CH][YROW]

    const int blk   = blockIdx.x;
    const int wtile = blk & (NWT - 1);
    const int bh    = blk >> 1;
    const int b     = bh / H_;
    const int h     = bh % H_;
    const int w0t   = wtile * WTILE;
    const int tid   = threadIdx.x;

    const size_t HW = (size_t)H_ * W_;
    const float* gx = x + ((size_t)(b * C_) * H_ + h) * W_ + w0t;
    const float* gy = y + ((size_t)(b * C_) * H_ + h) * W_ + w0t;

    const uint32_t xs_base = (uint32_t)__cvta_generic_to_shared(x_s);
    const uint32_t ys_base = (uint32_t)__cvta_generic_to_shared(y_s);

    // ---- prologue: zero the pad regions of both y buffers (tile 0 only) ----
    if (wtile == 0) {
        float4* ys4 = reinterpret_cast<float4*>(y_s);
        // 2 bufs * CH rows * (PAD/4) float4 = 256
        for (int i = tid; i < 2 * CH * (PAD / 4); i += NTHREADS) {
            int buf = i >> 7;                 // / 128
            int r   = (i >> 4) & (CH - 1);    // row within chunk
            int j   = i & 15;
            ys4[(buf * YCH_FLOATS + r * YROW) / 4 + j] =
                make_float4(0.f, 0.f, 0.f, 0.f);
        }
    }

    // ---- async load of one c-chunk into buffer `buf` ----
    auto load_chunk = [&](int buf, int ch) {
        const int c0 = ch * CH;
        // x: CH rows * 64 float4
        for (int i = tid; i < CH * (WTILE / 4); i += NTHREADS) {
            int cc = i >> 6, j = i & 63;
            uint32_t s = xs_base + (buf * XCH_FLOATS + cc * WTILE + 4 * j) * 4;
            cp_async16(s, gx + (size_t)(c0 + cc) * HW + 4 * j);
        }
        // y main: CH rows * 64 float4 at offset PAD
        for (int i = tid; i < CH * (WTILE / 4); i += NTHREADS) {
            int cc = i >> 6, j = i & 63;
            uint32_t s = ys_base + (buf * YCH_FLOATS + cc * YROW + PAD + 4 * j) * 4;
            cp_async16(s, gy + (size_t)(c0 + cc) * HW + 4 * j);
        }
        // y halo (tile 1 only): CH rows * 16 float4 at offset 0
        if (wtile != 0) {
            const float* gyh = gy - PAD;
            for (int i = tid; i < CH * (PAD / 4); i += NTHREADS) {
                int cc = i >> 4, j = i & 15;
                uint32_t s = ys_base + (buf * YCH_FLOATS + cc * YROW + 4 * j) * 4;
                cp_async16(s, gyh + (size_t)(c0 + cc) * HW + 4 * j);
            }
        }
        cp_commit();
    };

    load_chunk(0, 0);
    load_chunk(1, 1);

    // ---- compute mapping ----
    const int wblk = tid & (NWBLK - 1);
    const int dblk = tid >> 6;
    const int w0 = wblk * WT;
    const int d0 = dblk * DT;
    const int s  = PAD + w0 - d0 - 8;   // >= 16, multiple of 4

    unsigned long long acc2[DT][2];
    #pragma unroll
    for (int dd = 0; dd < DT; dd++) { acc2[dd][0] = 0ull; acc2[dd][1] = 0ull; }

    for (int ch = 0; ch < NCH; ch++) {
        if (ch + 1 < NCH) cp_wait1(); else cp_wait0();
        __syncthreads();

        const int buf = ch & 1;
        const float* xb = x_s + buf * XCH_FLOATS;
        const float* yb_s = y_s + buf * YCH_FLOATS;

        #pragma unroll 2
        for (int cc = 0; cc < CH; cc++) {
            const float* xr = xb + cc * WTILE;
            const float* yr = yb_s + cc * YROW;
            float4 xv  = *reinterpret_cast<const float4*>(xr + w0);
            float4 y0v = *reinterpret_cast<const float4*>(yr + s);
            float4 y1v = *reinterpret_cast<const float4*>(yr + s + 4);
            float4 y2v = *reinterpret_cast<const float4*>(yr + s + 8);
            float yv[12] = { y0v.x, y0v.y, y0v.z, y0v.w,
                             y1v.x, y1v.y, y1v.z, y1v.w,
                             y2v.x, y2v.y, y2v.z, y2v.w };
            unsigned long long x01 = pack2(xv.x, xv.y);
            unsigned long long x23 = pack2(xv.z, xv.w);
            unsigned long long p[11];
            #pragma unroll
            for (int k = 1; k <= 10; k++) p[k] = pack2(yv[k], yv[k + 1]);
            #pragma unroll
            for (int dd = 0; dd < DT; dd++) {
                ffma2(acc2[dd][0], x01, p[8 - dd]);
                ffma2(acc2[dd][1], x23, p[10 - dd]);
            }
        }

        __syncthreads();
        if (ch + 2 < NCH) load_chunk(ch & 1, ch + 2);
    }

    // ---- store (mean over C) ----
    const float inv = 1.0f / (float)C_;
    #pragma unroll
    for (int dd = 0; dd < DT; dd++) {
        int d = d0 + dd;
        float a0, a1, a2, a3;
        unpack2(acc2[dd][0], a0, a1);
        unpack2(acc2[dd][1], a2, a3);
        float4 v = make_float4(a0 * inv, a1 * inv, a2 * inv, a3 * inv);
        float* op = out + (((size_t)(b * D_ + d)) * H_ + h) * W_ + w0t + w0;
        *reinterpret_cast<float4*>(op) = v;
    }
}

extern "C" void kernel_launch(void* const* d_in, const int* in_sizes, int n_in,
                              void* d_out, int out_size)
{
    const float* x = (const float*)d_in[0];
    const float* y = (const float*)d_in[1];
    float* out = (float*)d_out;

    static bool attr_set = false;
    if (!attr_set) {
        cudaFuncSetAttribute(corr_kernel,
                             cudaFuncAttributeMaxDynamicSharedMemorySize,
                             SMEM_BYTES);
        attr_set = true;
    }

    corr_kernel<<<B_ * H_ * NWT, NTHREADS, SMEM_BYTES>>>(x, y, out);
}